// round 1
// baseline (speedup 1.0000x reference)
#include <cuda_runtime.h>
#include <cuda_bf16.h>
#include <math.h>

// Problem constants
#define B_  2
#define S_  4096
#define D_  1024
#define H_  16
#define HD_ 64
#define M_  512
#define L_  1024
#define HID_ 2816
#define NSTEP 8

// ---------------------------------------------------------------------------
// Scratch (device globals; no allocation allowed)
// ---------------------------------------------------------------------------
__device__ float g_allout[B_ * S_ * D_];     // per-step om_new, (B, S, D)
__device__ float g_a   [B_ * M_ * D_];       // om @ wm (accumulates ffn)
__device__ float g_hn  [B_ * M_ * D_];       // rmsnorm(a)
__device__ float g_t1  [B_ * M_ * HID_];     // h @ w1 -> silu-gated
__device__ float g_t3  [B_ * M_ * HID_];     // h @ w3
__device__ float g_m2  [B_ * M_ * D_];       // rmsnorm(a, mem_norm)
__device__ float g_q   [B_ * M_ * D_];       // xq (positions 512..1023)
__device__ float g_k   [B_ * L_ * D_];       // concat(mk, xk)
__device__ float g_v   [B_ * L_ * D_];       // concat(mv, xv)

// ---------------------------------------------------------------------------
// Batched SGEMM: C[z] = A[z] (Mrows x K, row-major) @ B (K x N, row-major)
// Mrows per batch = gridDim.y * 128. Optional accumulate into C.
// ---------------------------------------------------------------------------
#define GBM 128
#define GBN 128
#define GBK 8

template <bool ACC>
__global__ __launch_bounds__(256)
void sgemm_kernel(const float* __restrict__ A, long long aBatch,
                  const float* __restrict__ Bm,
                  float* __restrict__ C, long long cBatch,
                  int K, int N)
{
    const float* Ab = A + (long long)blockIdx.z * aBatch;
    float*       Cb = C + (long long)blockIdx.z * cBatch;
    const int m0 = blockIdx.y * GBM;
    const int n0 = blockIdx.x * GBN;

    __shared__ float As[GBK][GBM + 4];
    __shared__ float Bs[GBK][GBN + 4];

    const int tid  = threadIdx.x;
    const int arow = tid >> 1, acol = (tid & 1) * 4;
    const int brow = tid >> 5, bcol = (tid & 31) * 4;
    const int tx = tid & 15, ty = tid >> 4;

    float acc[8][8];
    #pragma unroll
    for (int i = 0; i < 8; i++)
        #pragma unroll
        for (int j = 0; j < 8; j++) acc[i][j] = 0.f;

    for (int k0 = 0; k0 < K; k0 += GBK) {
        float4 av = *(const float4*)&Ab[(long long)(m0 + arow) * K + k0 + acol];
        As[acol + 0][arow] = av.x;
        As[acol + 1][arow] = av.y;
        As[acol + 2][arow] = av.z;
        As[acol + 3][arow] = av.w;
        *(float4*)&Bs[brow][bcol] =
            *(const float4*)&Bm[(long long)(k0 + brow) * N + n0 + bcol];
        __syncthreads();

        #pragma unroll
        for (int kk = 0; kk < GBK; kk++) {
            float4 a0 = *(const float4*)&As[kk][ty * 8];
            float4 a1 = *(const float4*)&As[kk][ty * 8 + 4];
            float4 b0 = *(const float4*)&Bs[kk][tx * 8];
            float4 b1 = *(const float4*)&Bs[kk][tx * 8 + 4];
            float ra[8] = {a0.x, a0.y, a0.z, a0.w, a1.x, a1.y, a1.z, a1.w};
            float rb[8] = {b0.x, b0.y, b0.z, b0.w, b1.x, b1.y, b1.z, b1.w};
            #pragma unroll
            for (int i = 0; i < 8; i++)
                #pragma unroll
                for (int j = 0; j < 8; j++)
                    acc[i][j] = fmaf(ra[i], rb[j], acc[i][j]);
        }
        __syncthreads();
    }

    #pragma unroll
    for (int i = 0; i < 8; i++) {
        float* cp = Cb + (long long)(m0 + ty * 8 + i) * N + n0 + tx * 8;
        float4 c0 = make_float4(acc[i][0], acc[i][1], acc[i][2], acc[i][3]);
        float4 c1 = make_float4(acc[i][4], acc[i][5], acc[i][6], acc[i][7]);
        if (ACC) {
            float4 o0 = *(const float4*)cp;
            float4 o1 = *(const float4*)(cp + 4);
            c0.x += o0.x; c0.y += o0.y; c0.z += o0.z; c0.w += o0.w;
            c1.x += o1.x; c1.y += o1.y; c1.z += o1.z; c1.w += o1.w;
        }
        *(float4*)cp       = c0;
        *(float4*)(cp + 4) = c1;
    }
}

// ---------------------------------------------------------------------------
// RMSNorm: one block per row of 1024 elements
// ---------------------------------------------------------------------------
__global__ __launch_bounds__(256)
void rmsnorm_kernel(const float* __restrict__ x, const float* __restrict__ w,
                    float* __restrict__ o)
{
    const int row = blockIdx.x;
    const int tid = threadIdx.x;
    const float4 v = *(const float4*)(x + (size_t)row * D_ + tid * 4);
    float ss = v.x * v.x + v.y * v.y + v.z * v.z + v.w * v.w;
    #pragma unroll
    for (int off = 16; off; off >>= 1)
        ss += __shfl_xor_sync(0xffffffffu, ss, off);
    __shared__ float ws[8];
    __shared__ float s_inv;
    if ((tid & 31) == 0) ws[tid >> 5] = ss;
    __syncthreads();
    if (tid == 0) {
        float t = 0.f;
        #pragma unroll
        for (int i = 0; i < 8; i++) t += ws[i];
        s_inv = rsqrtf(t * (1.0f / D_) + 1e-5f);
    }
    __syncthreads();
    const float inv = s_inv;
    const float4 wv = *(const float4*)(w + tid * 4);
    float4 ov;
    ov.x = v.x * inv * wv.x;
    ov.y = v.y * inv * wv.y;
    ov.z = v.z * inv * wv.z;
    ov.w = v.w * inv * wv.w;
    *(float4*)(o + (size_t)row * D_ + tid * 4) = ov;
}

// ---------------------------------------------------------------------------
// SwiGLU gate: t1 = silu(t1) * t3
// ---------------------------------------------------------------------------
__global__ void silu_gate_kernel(float* __restrict__ t1,
                                 const float* __restrict__ t3, int n)
{
    int i = blockIdx.x * blockDim.x + threadIdx.x;
    if (i < n) {
        float a = t1[i];
        float s = a / (1.f + __expf(-a));
        t1[i] = s * t3[i];
    }
}

// ---------------------------------------------------------------------------
// RoPE in place on (B, rowsPerB, 1024) with positions posOff + row
// ---------------------------------------------------------------------------
__global__ void rope_kernel(float* __restrict__ t,
                            const float* __restrict__ cosT,
                            const float* __restrict__ sinT,
                            int rowsPerB, int posOff, int nPairs)
{
    int id = blockIdx.x * blockDim.x + threadIdx.x;
    if (id >= nPairs) return;
    int pair = id & 511;         // 512 pairs per 1024-wide row
    int row  = id >> 9;          // global row (b*rowsPerB + r)
    int pos  = posOff + (row % rowsPerB);
    int i    = pair & 31;        // index within head (HD/2 = 32)
    float c = cosT[pos * 32 + i];
    float s = sinT[pos * 32 + i];
    float2* p = (float2*)(t + (size_t)row * D_ + pair * 2);
    float2 v = *p;
    float2 o;
    o.x = v.x * c - v.y * s;
    o.y = v.x * s + v.y * c;
    *p = o;
}

// ---------------------------------------------------------------------------
// Flash-style causal attention for the x-part queries only (rows M..L-1).
// Grid: (qtile=8, h=16, b=2), 256 threads. BM=BN=64, HD=64.
// Q: (B, M, D) roped; K,V: (B, L, D). Out -> g_allout rows [b, outRowOff+q].
// ---------------------------------------------------------------------------
#define ALD 65   // padded row stride (floats) for conflict-free scalar LDS
#define ATTN_SMEM ((4 * 64 * ALD + 3 * 64) * (int)sizeof(float))

__global__ __launch_bounds__(256)
void attn_kernel(const float* __restrict__ Q, const float* __restrict__ Kt,
                 const float* __restrict__ V, float* __restrict__ Out,
                 int outRowOff)
{
    extern __shared__ float sm[];
    float* Qs   = sm;
    float* Ks   = Qs + 64 * ALD;
    float* Vs   = Ks + 64 * ALD;
    float* Ss   = Vs + 64 * ALD;
    float* mrow = Ss + 64 * ALD;
    float* lrow = mrow + 64;
    float* crow = lrow + 64;

    const int b  = blockIdx.z;
    const int h  = blockIdx.y;
    const int qt = blockIdx.x;
    const int tid = threadIdx.x;
    const int tx = tid & 15, ty = tid >> 4;
    const int q0 = qt * 64;              // within x-part [0, 512)
    const float scale = 0.125f;          // 1/sqrt(64)

    // Load Q tile
    for (int e = tid; e < 64 * 16; e += 256) {
        int i = e >> 4, d4 = (e & 15) * 4;
        float4 v = *(const float4*)&Q[((size_t)(b * M_ + q0 + i)) * D_ + h * HD_ + d4];
        Qs[i * ALD + d4 + 0] = v.x;
        Qs[i * ALD + d4 + 1] = v.y;
        Qs[i * ALD + d4 + 2] = v.z;
        Qs[i * ALD + d4 + 3] = v.w;
    }
    if (tid < 64) { mrow[tid] = -1e30f; lrow[tid] = 0.f; }
    float acc[4][4];
    #pragma unroll
    for (int i = 0; i < 4; i++)
        #pragma unroll
        for (int j = 0; j < 4; j++) acc[i][j] = 0.f;
    __syncthreads();

    const int nkt = qt + 9;              // key tiles needed (causal)
    for (int kt = 0; kt < nkt; kt++) {
        // Load K and V tiles
        for (int e = tid; e < 64 * 16; e += 256) {
            int j = e >> 4, d4 = (e & 15) * 4;
            size_t base = ((size_t)(b * L_ + kt * 64 + j)) * D_ + h * HD_ + d4;
            float4 kv = *(const float4*)&Kt[base];
            Ks[j * ALD + d4 + 0] = kv.x;
            Ks[j * ALD + d4 + 1] = kv.y;
            Ks[j * ALD + d4 + 2] = kv.z;
            Ks[j * ALD + d4 + 3] = kv.w;
            float4 vv = *(const float4*)&V[base];
            Vs[j * ALD + d4 + 0] = vv.x;
            Vs[j * ALD + d4 + 1] = vv.y;
            Vs[j * ALD + d4 + 2] = vv.z;
            Vs[j * ALD + d4 + 3] = vv.w;
        }
        __syncthreads();

        // S = Q K^T  (4x4 per thread)
        float s4[4][4];
        #pragma unroll
        for (int i = 0; i < 4; i++)
            #pragma unroll
            for (int j = 0; j < 4; j++) s4[i][j] = 0.f;
        for (int d = 0; d < 64; d++) {
            float rq[4], rk[4];
            #pragma unroll
            for (int ii = 0; ii < 4; ii++) rq[ii] = Qs[(ty * 4 + ii) * ALD + d];
            #pragma unroll
            for (int jj = 0; jj < 4; jj++) rk[jj] = Ks[(tx * 4 + jj) * ALD + d];
            #pragma unroll
            for (int ii = 0; ii < 4; ii++)
                #pragma unroll
                for (int jj = 0; jj < 4; jj++)
                    s4[ii][jj] = fmaf(rq[ii], rk[jj], s4[ii][jj]);
        }
        // scale + causal mask + store to Ss
        const int qg0 = M_ + q0;
        #pragma unroll
        for (int ii = 0; ii < 4; ii++) {
            int qi = qg0 + ty * 4 + ii;
            #pragma unroll
            for (int jj = 0; jj < 4; jj++) {
                int kj = kt * 64 + tx * 4 + jj;
                float val = (kj <= qi) ? s4[ii][jj] * scale : -1e30f;
                Ss[(ty * 4 + ii) * ALD + tx * 4 + jj] = val;
            }
        }
        __syncthreads();

        // Online softmax per row (threads 0..63)
        if (tid < 64) {
            float mold = mrow[tid];
            float mx = mold;
            for (int j = 0; j < 64; j++) mx = fmaxf(mx, Ss[tid * ALD + j]);
            float c = __expf(mold - mx);
            float sum = 0.f;
            for (int j = 0; j < 64; j++) {
                float p = __expf(Ss[tid * ALD + j] - mx);
                Ss[tid * ALD + j] = p;
                sum += p;
            }
            mrow[tid] = mx;
            lrow[tid] = lrow[tid] * c + sum;
            crow[tid] = c;
        }
        __syncthreads();

        // Rescale + O += P @ V
        float cc[4];
        #pragma unroll
        for (int ii = 0; ii < 4; ii++) cc[ii] = crow[ty * 4 + ii];
        #pragma unroll
        for (int ii = 0; ii < 4; ii++)
            #pragma unroll
            for (int dd = 0; dd < 4; dd++) acc[ii][dd] *= cc[ii];
        for (int j = 0; j < 64; j++) {
            float rp[4], rv[4];
            #pragma unroll
            for (int ii = 0; ii < 4; ii++) rp[ii] = Ss[(ty * 4 + ii) * ALD + j];
            #pragma unroll
            for (int dd = 0; dd < 4; dd++) rv[dd] = Vs[j * ALD + tx * 4 + dd];
            #pragma unroll
            for (int ii = 0; ii < 4; ii++)
                #pragma unroll
                for (int dd = 0; dd < 4; dd++)
                    acc[ii][dd] = fmaf(rp[ii], rv[dd], acc[ii][dd]);
        }
        __syncthreads();
    }

    // Finalize: divide by l, write out
    if (tid < 64) crow[tid] = 1.f / lrow[tid];
    __syncthreads();
    #pragma unroll
    for (int ii = 0; ii < 4; ii++) {
        float inv = crow[ty * 4 + ii];
        int grow = b * S_ + outRowOff + q0 + ty * 4 + ii;
        float4 o;
        o.x = acc[ii][0] * inv;
        o.y = acc[ii][1] * inv;
        o.z = acc[ii][2] * inv;
        o.w = acc[ii][3] * inv;
        *(float4*)&Out[(size_t)grow * D_ + h * HD_ + tx * 4] = o;
    }
}

// ---------------------------------------------------------------------------
// Launch
// ---------------------------------------------------------------------------
extern "C" void kernel_launch(void* const* d_in, const int* in_sizes, int n_in,
                              void* d_out, int out_size)
{
    const float* x        = (const float*)d_in[0];
    const float* cosT     = (const float*)d_in[1];
    const float* sinT     = (const float*)d_in[2];
    const float* wq       = (const float*)d_in[3];
    const float* wk       = (const float*)d_in[4];
    const float* wv       = (const float*)d_in[5];
    const float* wo       = (const float*)d_in[6];
    const float* wm       = (const float*)d_in[7];
    const float* wkm      = (const float*)d_in[8];
    const float* wvm      = (const float*)d_in[9];
    const float* w1       = (const float*)d_in[10];
    const float* w3       = (const float*)d_in[11];
    const float* w2       = (const float*)d_in[12];
    const float* ffn_nw   = (const float*)d_in[13];
    const float* mem_nw   = (const float*)d_in[14];
    const float* omem     = (const float*)d_in[15];
    float* out = (float*)d_out;

    float *p_allout, *p_a, *p_hn, *p_t1, *p_t3, *p_m2, *p_q, *p_k, *p_v;
    cudaGetSymbolAddress((void**)&p_allout, g_allout);
    cudaGetSymbolAddress((void**)&p_a,  g_a);
    cudaGetSymbolAddress((void**)&p_hn, g_hn);
    cudaGetSymbolAddress((void**)&p_t1, g_t1);
    cudaGetSymbolAddress((void**)&p_t3, g_t3);
    cudaGetSymbolAddress((void**)&p_m2, g_m2);
    cudaGetSymbolAddress((void**)&p_q,  g_q);
    cudaGetSymbolAddress((void**)&p_k,  g_k);
    cudaGetSymbolAddress((void**)&p_v,  g_v);

    cudaFuncSetAttribute(attn_kernel,
                         cudaFuncAttributeMaxDynamicSharedMemorySize, ATTN_SMEM);

    const dim3 g1024(D_ / GBN, M_ / GBM, B_);     // (8, 4, 2)
    const dim3 g2816(HID_ / GBN, M_ / GBM, B_);   // (22, 4, 2)

    for (int s = 0; s < NSTEP; s++) {
        const float* om = (s == 0) ? omem : (p_allout + (size_t)(s - 1) * M_ * D_);
        const long long omB = (s == 0) ? 0LL : (long long)S_ * D_;

        // a = om @ wm
        sgemm_kernel<false><<<g1024, 256>>>(om, omB, wm, p_a, (long long)M_ * D_, D_, D_);
        // hn = rmsnorm(a, ffn_norm_w)
        rmsnorm_kernel<<<B_ * M_, 256>>>(p_a, ffn_nw, p_hn);
        // t1 = hn @ w1 ; t3 = hn @ w3
        sgemm_kernel<false><<<g2816, 256>>>(p_hn, (long long)M_ * D_, w1, p_t1, (long long)M_ * HID_, D_, HID_);
        sgemm_kernel<false><<<g2816, 256>>>(p_hn, (long long)M_ * D_, w3, p_t3, (long long)M_ * HID_, D_, HID_);
        // t1 = silu(t1) * t3
        silu_gate_kernel<<<(B_ * M_ * HID_ + 255) / 256, 256>>>(p_t1, p_t3, B_ * M_ * HID_);
        // a += t1 @ w2
        sgemm_kernel<true><<<g1024, 256>>>(p_t1, (long long)M_ * HID_, w2, p_a, (long long)M_ * D_, HID_, D_);
        // m2 = rmsnorm(a, mem_norm_w)
        rmsnorm_kernel<<<B_ * M_, 256>>>(p_a, mem_nw, p_m2);
        // mk -> k[:, :512], mv -> v[:, :512]
        sgemm_kernel<false><<<g1024, 256>>>(p_m2, (long long)M_ * D_, wkm, p_k, (long long)L_ * D_, D_, D_);
        sgemm_kernel<false><<<g1024, 256>>>(p_m2, (long long)M_ * D_, wvm, p_v, (long long)L_ * D_, D_, D_);
        // xq, xk -> k[:, 512:], xv -> v[:, 512:]
        const float* xs = x + (size_t)s * M_ * D_;
        sgemm_kernel<false><<<g1024, 256>>>(xs, (long long)S_ * D_, wq, p_q, (long long)M_ * D_, D_, D_);
        sgemm_kernel<false><<<g1024, 256>>>(xs, (long long)S_ * D_, wk, p_k + (size_t)M_ * D_, (long long)L_ * D_, D_, D_);
        sgemm_kernel<false><<<g1024, 256>>>(xs, (long long)S_ * D_, wv, p_v + (size_t)M_ * D_, (long long)L_ * D_, D_, D_);
        // RoPE: k (positions 0..1023), q (positions 512..1023)
        {
            int nk = B_ * L_ * (D_ / 2);
            rope_kernel<<<(nk + 255) / 256, 256>>>(p_k, cosT, sinT, L_, 0, nk);
            int nq = B_ * M_ * (D_ / 2);
            rope_kernel<<<(nq + 255) / 256, 256>>>(p_q, cosT, sinT, M_, M_, nq);
        }
        // Attention (x-part queries only) -> g_allout[:, s*512 : (s+1)*512]
        attn_kernel<<<dim3(M_ / 64, H_, B_), 256, ATTN_SMEM>>>(p_q, p_k, p_v, p_allout, s * M_);
    }

    // out = allout @ wo   (M = B*S = 8192 contiguous rows)
    sgemm_kernel<false><<<dim3(D_ / GBN, (B_ * S_) / GBM, 1), 256>>>(
        p_allout, 0LL, wo, out, 0LL, D_, D_);
}

// round 3
// speedup vs baseline: 2.7893x; 2.7893x over previous
#include <cuda_runtime.h>
#include <cuda_bf16.h>
#include <cstdint>
#include <math.h>

// Problem constants
#define B_  2
#define S_  4096
#define D_  1024
#define H_  16
#define HD_ 64
#define M_  512
#define L_  1024
#define HID_ 2816
#define NSTEP 8

// ---------------------------------------------------------------------------
// Scratch (device globals; no allocation allowed)
// ---------------------------------------------------------------------------
__device__ float g_allout[B_ * S_ * D_];
__device__ float g_a   [B_ * M_ * D_];
__device__ float g_hn  [B_ * M_ * D_];
__device__ float g_t1  [B_ * M_ * HID_];
__device__ float g_t3  [B_ * M_ * HID_];
__device__ float g_m2  [B_ * M_ * D_];
__device__ float g_q   [B_ * M_ * D_];
__device__ float g_k   [B_ * L_ * D_];
__device__ float g_v   [B_ * L_ * D_];

// ---------------------------------------------------------------------------
// Warp-level bf16 MMA (HMMA) helper — valid under compute_103 (non-'a') target
// ---------------------------------------------------------------------------
__device__ __forceinline__ void mma16816(float* c,
                                         uint32_t a0, uint32_t a1, uint32_t a2, uint32_t a3,
                                         uint32_t b0, uint32_t b1)
{
    asm volatile(
        "mma.sync.aligned.m16n8k16.row.col.f32.bf16.bf16.f32 "
        "{%0,%1,%2,%3}, {%4,%5,%6,%7}, {%8,%9}, {%0,%1,%2,%3};"
        : "+f"(c[0]), "+f"(c[1]), "+f"(c[2]), "+f"(c[3])
        : "r"(a0), "r"(a1), "r"(a2), "r"(a3), "r"(b0), "r"(b1));
}

// ---------------------------------------------------------------------------
// Split-bf16 GEMM on tensor cores.
// C[z][mat] = A[z] (rows x K, row-major) @ B[mat] (K x N, row-major), fp32 io.
// acc = Ah*Bh + Ah*Bl + Al*Bh  (bf16 hi/lo split, ~1e-5 rel err)
// Tile 128x128, BK=32, 256 threads (8 warps as 2M x 4N, warp tile 64x32).
// grid: (nmat * tilesN, rows/128, batch).
// ---------------------------------------------------------------------------
#define BK 32
#define AST 40                      // bf16 row stride (20 words: conflict-free)
#define A_HALF (128 * AST * 2)      // 10240 bytes per half (hi or lo)
#define GEMM_SMEM (4 * A_HALF)      // Ahi, Alo, Bhi, Blo = 40960 bytes

template <bool ACC>
__global__ __launch_bounds__(256, 2)
void mma_gemm_kernel(const float* __restrict__ A, long long aBatch,
                     const float* __restrict__ B0, const float* __restrict__ B1,
                     const float* __restrict__ B2,
                     float* __restrict__ C0, float* __restrict__ C1, float* __restrict__ C2,
                     long long cB0, long long cB1, long long cB2,
                     int K, int N, int tilesN)
{
    extern __shared__ char smem[];
    __nv_bfloat16* Ahi = (__nv_bfloat16*)smem;
    __nv_bfloat16* Alo = (__nv_bfloat16*)(smem + A_HALF);
    __nv_bfloat16* Bhi = (__nv_bfloat16*)(smem + 2 * A_HALF);
    __nv_bfloat16* Blo = (__nv_bfloat16*)(smem + 3 * A_HALF);

    const int tid = threadIdx.x;
    const int wid = tid >> 5, lane = tid & 31;
    const int wm = wid & 1, wn = wid >> 1;           // 2 x 4 warp grid
    const int r  = lane >> 2, qc = (lane & 3) * 2;   // fragment coords

    const int tn  = blockIdx.x % tilesN;
    const int mat = blockIdx.x / tilesN;
    const int bz  = blockIdx.z;
    const int m0  = blockIdx.y * 128;
    const int n0  = tn * 128;

    const float* Bm = (mat == 0) ? B0 : ((mat == 1) ? B1 : B2);
    float*       Cm = (mat == 0) ? C0 : ((mat == 1) ? C1 : C2);
    const long long cB = (mat == 0) ? cB0 : ((mat == 1) ? cB1 : cB2);

    const float* Ab = A + (long long)bz * aBatch + (long long)m0 * K;

    // Load thread mappings
    const int ar  = tid >> 1,  akb = (tid & 1) * 16;   // A: 128 rows x 32 k
    const int bn  = tid & 127, bkb = (tid >> 7) * 16;  // B: col per thread, 16 k

    float4 pa[4];
    float  pb[16];

    // Preload chunk 0
    {
        const float* Ap = Ab + (size_t)ar * K + akb;
        #pragma unroll
        for (int j = 0; j < 4; j++) pa[j] = *(const float4*)(Ap + j * 4);
        const float* Bp = Bm + (size_t)bkb * N + n0 + bn;
        #pragma unroll
        for (int j = 0; j < 16; j++) pb[j] = Bp[(size_t)j * N];
    }

    float acc[4][4][4];
    #pragma unroll
    for (int i = 0; i < 4; i++)
        #pragma unroll
        for (int j = 0; j < 4; j++)
            #pragma unroll
            for (int e = 0; e < 4; e++) acc[i][j][e] = 0.f;

    const int NC = K / BK;
    #pragma unroll 1
    for (int kc = 0; kc < NC; kc++) {
        // ---- convert + store current chunk to smem ----
        #pragma unroll
        for (int j = 0; j < 4; j++) {
            float4 v = pa[j];
            __nv_bfloat16 h0 = __float2bfloat16(v.x);
            __nv_bfloat16 h1 = __float2bfloat16(v.y);
            __nv_bfloat16 h2 = __float2bfloat16(v.z);
            __nv_bfloat16 h3 = __float2bfloat16(v.w);
            __nv_bfloat162 hp0 = __halves2bfloat162(h0, h1);
            __nv_bfloat162 hp1 = __halves2bfloat162(h2, h3);
            __nv_bfloat162 lp0 = __floats2bfloat162_rn(v.x - __bfloat162float(h0),
                                                       v.y - __bfloat162float(h1));
            __nv_bfloat162 lp1 = __floats2bfloat162_rn(v.z - __bfloat162float(h2),
                                                       v.w - __bfloat162float(h3));
            int off = ar * AST + akb + j * 4;
            *(uint2*)&Ahi[off] = make_uint2(*(uint32_t*)&hp0, *(uint32_t*)&hp1);
            *(uint2*)&Alo[off] = make_uint2(*(uint32_t*)&lp0, *(uint32_t*)&lp1);
        }
        #pragma unroll
        for (int g = 0; g < 4; g++) {
            __nv_bfloat16 h0 = __float2bfloat16(pb[g * 4 + 0]);
            __nv_bfloat16 h1 = __float2bfloat16(pb[g * 4 + 1]);
            __nv_bfloat16 h2 = __float2bfloat16(pb[g * 4 + 2]);
            __nv_bfloat16 h3 = __float2bfloat16(pb[g * 4 + 3]);
            __nv_bfloat162 hp0 = __halves2bfloat162(h0, h1);
            __nv_bfloat162 hp1 = __halves2bfloat162(h2, h3);
            __nv_bfloat162 lp0 = __floats2bfloat162_rn(pb[g*4+0] - __bfloat162float(h0),
                                                       pb[g*4+1] - __bfloat162float(h1));
            __nv_bfloat162 lp1 = __floats2bfloat162_rn(pb[g*4+2] - __bfloat162float(h2),
                                                       pb[g*4+3] - __bfloat162float(h3));
            int off = bn * AST + bkb + g * 4;
            *(uint2*)&Bhi[off] = make_uint2(*(uint32_t*)&hp0, *(uint32_t*)&hp1);
            *(uint2*)&Blo[off] = make_uint2(*(uint32_t*)&lp0, *(uint32_t*)&lp1);
        }
        __syncthreads();

        // ---- prefetch next chunk (LDG latency overlaps MMA below) ----
        if (kc + 1 < NC) {
            const int k0n = (kc + 1) * BK;
            const float* Ap = Ab + (size_t)ar * K + k0n + akb;
            #pragma unroll
            for (int j = 0; j < 4; j++) pa[j] = *(const float4*)(Ap + j * 4);
            const float* Bp = Bm + (size_t)(k0n + bkb) * N + n0 + bn;
            #pragma unroll
            for (int j = 0; j < 16; j++) pb[j] = Bp[(size_t)j * N];
        }

        // ---- MMA over this chunk: 2 k-steps of 16 ----
        #pragma unroll
        for (int ks = 0; ks < 2; ks++) {
            const int kb = ks * 16;
            uint32_t bhf[4][2], blf[4][2];
            #pragma unroll
            for (int nt = 0; nt < 4; nt++) {
                int nb = (wn * 32 + nt * 8 + r) * AST + kb + qc;
                bhf[nt][0] = *(const uint32_t*)&Bhi[nb];
                bhf[nt][1] = *(const uint32_t*)&Bhi[nb + 8];
                blf[nt][0] = *(const uint32_t*)&Blo[nb];
                blf[nt][1] = *(const uint32_t*)&Blo[nb + 8];
            }
            #pragma unroll
            for (int mt = 0; mt < 4; mt++) {
                int rb = (wm * 64 + mt * 16 + r) * AST + kb + qc;
                uint32_t ah0 = *(const uint32_t*)&Ahi[rb];
                uint32_t ah1 = *(const uint32_t*)&Ahi[rb + 8 * AST];
                uint32_t ah2 = *(const uint32_t*)&Ahi[rb + 8];
                uint32_t ah3 = *(const uint32_t*)&Ahi[rb + 8 * AST + 8];
                uint32_t al0 = *(const uint32_t*)&Alo[rb];
                uint32_t al1 = *(const uint32_t*)&Alo[rb + 8 * AST];
                uint32_t al2 = *(const uint32_t*)&Alo[rb + 8];
                uint32_t al3 = *(const uint32_t*)&Alo[rb + 8 * AST + 8];
                #pragma unroll
                for (int nt = 0; nt < 4; nt++) {
                    mma16816(acc[mt][nt], ah0, ah1, ah2, ah3, bhf[nt][0], bhf[nt][1]);
                    mma16816(acc[mt][nt], ah0, ah1, ah2, ah3, blf[nt][0], blf[nt][1]);
                    mma16816(acc[mt][nt], al0, al1, al2, al3, bhf[nt][0], bhf[nt][1]);
                }
            }
        }
        __syncthreads();
    }

    // ---- epilogue ----
    float* Cb = Cm + (long long)bz * cB;
    #pragma unroll
    for (int mt = 0; mt < 4; mt++) {
        int row0 = m0 + wm * 64 + mt * 16 + r;
        #pragma unroll
        for (int nt = 0; nt < 4; nt++) {
            int col = n0 + wn * 32 + nt * 8 + qc;
            float* p0 = Cb + (size_t)row0 * N + col;
            float* p1 = Cb + (size_t)(row0 + 8) * N + col;
            float2 v0 = make_float2(acc[mt][nt][0], acc[mt][nt][1]);
            float2 v1 = make_float2(acc[mt][nt][2], acc[mt][nt][3]);
            if (ACC) {
                float2 o0 = *(const float2*)p0;
                float2 o1 = *(const float2*)p1;
                v0.x += o0.x; v0.y += o0.y;
                v1.x += o1.x; v1.y += o1.y;
            }
            *(float2*)p0 = v0;
            *(float2*)p1 = v1;
        }
    }
}

// ---------------------------------------------------------------------------
// RMSNorm
// ---------------------------------------------------------------------------
__global__ __launch_bounds__(256)
void rmsnorm_kernel(const float* __restrict__ x, const float* __restrict__ w,
                    float* __restrict__ o)
{
    const int row = blockIdx.x;
    const int tid = threadIdx.x;
    const float4 v = *(const float4*)(x + (size_t)row * D_ + tid * 4);
    float ss = v.x * v.x + v.y * v.y + v.z * v.z + v.w * v.w;
    #pragma unroll
    for (int off = 16; off; off >>= 1)
        ss += __shfl_xor_sync(0xffffffffu, ss, off);
    __shared__ float ws[8];
    __shared__ float s_inv;
    if ((tid & 31) == 0) ws[tid >> 5] = ss;
    __syncthreads();
    if (tid == 0) {
        float t = 0.f;
        #pragma unroll
        for (int i = 0; i < 8; i++) t += ws[i];
        s_inv = rsqrtf(t * (1.0f / D_) + 1e-5f);
    }
    __syncthreads();
    const float inv = s_inv;
    const float4 wv = *(const float4*)(w + tid * 4);
    float4 ov;
    ov.x = v.x * inv * wv.x;
    ov.y = v.y * inv * wv.y;
    ov.z = v.z * inv * wv.z;
    ov.w = v.w * inv * wv.w;
    *(float4*)(o + (size_t)row * D_ + tid * 4) = ov;
}

// ---------------------------------------------------------------------------
// SwiGLU gate
// ---------------------------------------------------------------------------
__global__ void silu_gate_kernel(float* __restrict__ t1,
                                 const float* __restrict__ t3, int n)
{
    int i = blockIdx.x * blockDim.x + threadIdx.x;
    if (i < n) {
        float a = t1[i];
        float s = a / (1.f + __expf(-a));
        t1[i] = s * t3[i];
    }
}

// ---------------------------------------------------------------------------
// RoPE
// ---------------------------------------------------------------------------
__global__ void rope_kernel(float* __restrict__ t,
                            const float* __restrict__ cosT,
                            const float* __restrict__ sinT,
                            int rowsPerB, int posOff, int nPairs)
{
    int id = blockIdx.x * blockDim.x + threadIdx.x;
    if (id >= nPairs) return;
    int pair = id & 511;
    int row  = id >> 9;
    int pos  = posOff + (row % rowsPerB);
    int i    = pair & 31;
    float c = cosT[pos * 32 + i];
    float s = sinT[pos * 32 + i];
    float2* p = (float2*)(t + (size_t)row * D_ + pair * 2);
    float2 v = *p;
    float2 o;
    o.x = v.x * c - v.y * s;
    o.y = v.x * s + v.y * c;
    *p = o;
}

// ---------------------------------------------------------------------------
// Flash-style causal attention (x-part queries only)
// ---------------------------------------------------------------------------
#define ALD 65
#define ATTN_SMEM ((4 * 64 * ALD + 3 * 64) * (int)sizeof(float))

__global__ __launch_bounds__(256)
void attn_kernel(const float* __restrict__ Q, const float* __restrict__ Kt,
                 const float* __restrict__ V, float* __restrict__ Out,
                 int outRowOff)
{
    extern __shared__ float sm[];
    float* Qs   = sm;
    float* Ks   = Qs + 64 * ALD;
    float* Vs   = Ks + 64 * ALD;
    float* Ss   = Vs + 64 * ALD;
    float* mrow = Ss + 64 * ALD;
    float* lrow = mrow + 64;
    float* crow = lrow + 64;

    const int b  = blockIdx.z;
    const int h  = blockIdx.y;
    const int qt = blockIdx.x;
    const int tid = threadIdx.x;
    const int tx = tid & 15, ty = tid >> 4;
    const int q0 = qt * 64;
    const float scale = 0.125f;

    for (int e = tid; e < 64 * 16; e += 256) {
        int i = e >> 4, d4 = (e & 15) * 4;
        float4 v = *(const float4*)&Q[((size_t)(b * M_ + q0 + i)) * D_ + h * HD_ + d4];
        Qs[i * ALD + d4 + 0] = v.x;
        Qs[i * ALD + d4 + 1] = v.y;
        Qs[i * ALD + d4 + 2] = v.z;
        Qs[i * ALD + d4 + 3] = v.w;
    }
    if (tid < 64) { mrow[tid] = -1e30f; lrow[tid] = 0.f; }
    float acc[4][4];
    #pragma unroll
    for (int i = 0; i < 4; i++)
        #pragma unroll
        for (int j = 0; j < 4; j++) acc[i][j] = 0.f;
    __syncthreads();

    const int nkt = qt + 9;
    for (int kt = 0; kt < nkt; kt++) {
        for (int e = tid; e < 64 * 16; e += 256) {
            int j = e >> 4, d4 = (e & 15) * 4;
            size_t base = ((size_t)(b * L_ + kt * 64 + j)) * D_ + h * HD_ + d4;
            float4 kv = *(const float4*)&Kt[base];
            Ks[j * ALD + d4 + 0] = kv.x;
            Ks[j * ALD + d4 + 1] = kv.y;
            Ks[j * ALD + d4 + 2] = kv.z;
            Ks[j * ALD + d4 + 3] = kv.w;
            float4 vv = *(const float4*)&V[base];
            Vs[j * ALD + d4 + 0] = vv.x;
            Vs[j * ALD + d4 + 1] = vv.y;
            Vs[j * ALD + d4 + 2] = vv.z;
            Vs[j * ALD + d4 + 3] = vv.w;
        }
        __syncthreads();

        float s4[4][4];
        #pragma unroll
        for (int i = 0; i < 4; i++)
            #pragma unroll
            for (int j = 0; j < 4; j++) s4[i][j] = 0.f;
        for (int d = 0; d < 64; d++) {
            float rq[4], rk[4];
            #pragma unroll
            for (int ii = 0; ii < 4; ii++) rq[ii] = Qs[(ty * 4 + ii) * ALD + d];
            #pragma unroll
            for (int jj = 0; jj < 4; jj++) rk[jj] = Ks[(tx * 4 + jj) * ALD + d];
            #pragma unroll
            for (int ii = 0; ii < 4; ii++)
                #pragma unroll
                for (int jj = 0; jj < 4; jj++)
                    s4[ii][jj] = fmaf(rq[ii], rk[jj], s4[ii][jj]);
        }
        const int qg0 = M_ + q0;
        #pragma unroll
        for (int ii = 0; ii < 4; ii++) {
            int qi = qg0 + ty * 4 + ii;
            #pragma unroll
            for (int jj = 0; jj < 4; jj++) {
                int kj = kt * 64 + tx * 4 + jj;
                float val = (kj <= qi) ? s4[ii][jj] * scale : -1e30f;
                Ss[(ty * 4 + ii) * ALD + tx * 4 + jj] = val;
            }
        }
        __syncthreads();

        if (tid < 64) {
            float mold = mrow[tid];
            float mx = mold;
            for (int j = 0; j < 64; j++) mx = fmaxf(mx, Ss[tid * ALD + j]);
            float c = __expf(mold - mx);
            float sum = 0.f;
            for (int j = 0; j < 64; j++) {
                float p = __expf(Ss[tid * ALD + j] - mx);
                Ss[tid * ALD + j] = p;
                sum += p;
            }
            mrow[tid] = mx;
            lrow[tid] = lrow[tid] * c + sum;
            crow[tid] = c;
        }
        __syncthreads();

        float cc[4];
        #pragma unroll
        for (int ii = 0; ii < 4; ii++) cc[ii] = crow[ty * 4 + ii];
        #pragma unroll
        for (int ii = 0; ii < 4; ii++)
            #pragma unroll
            for (int dd = 0; dd < 4; dd++) acc[ii][dd] *= cc[ii];
        for (int j = 0; j < 64; j++) {
            float rp[4], rv[4];
            #pragma unroll
            for (int ii = 0; ii < 4; ii++) rp[ii] = Ss[(ty * 4 + ii) * ALD + j];
            #pragma unroll
            for (int dd = 0; dd < 4; dd++) rv[dd] = Vs[j * ALD + tx * 4 + dd];
            #pragma unroll
            for (int ii = 0; ii < 4; ii++)
                #pragma unroll
                for (int dd = 0; dd < 4; dd++)
                    acc[ii][dd] = fmaf(rp[ii], rv[dd], acc[ii][dd]);
        }
        __syncthreads();
    }

    if (tid < 64) crow[tid] = 1.f / lrow[tid];
    __syncthreads();
    #pragma unroll
    for (int ii = 0; ii < 4; ii++) {
        float inv = crow[ty * 4 + ii];
        int grow = b * S_ + outRowOff + q0 + ty * 4 + ii;
        float4 o;
        o.x = acc[ii][0] * inv;
        o.y = acc[ii][1] * inv;
        o.z = acc[ii][2] * inv;
        o.w = acc[ii][3] * inv;
        *(float4*)&Out[(size_t)grow * D_ + h * HD_ + tx * 4] = o;
    }
}

// ---------------------------------------------------------------------------
// Launch
// ---------------------------------------------------------------------------
extern "C" void kernel_launch(void* const* d_in, const int* in_sizes, int n_in,
                              void* d_out, int out_size)
{
    const float* x        = (const float*)d_in[0];
    const float* cosT     = (const float*)d_in[1];
    const float* sinT     = (const float*)d_in[2];
    const float* wq       = (const float*)d_in[3];
    const float* wk       = (const float*)d_in[4];
    const float* wv       = (const float*)d_in[5];
    const float* wo       = (const float*)d_in[6];
    const float* wm       = (const float*)d_in[7];
    const float* wkm      = (const float*)d_in[8];
    const float* wvm      = (const float*)d_in[9];
    const float* w1       = (const float*)d_in[10];
    const float* w3       = (const float*)d_in[11];
    const float* w2       = (const float*)d_in[12];
    const float* ffn_nw   = (const float*)d_in[13];
    const float* mem_nw   = (const float*)d_in[14];
    const float* omem     = (const float*)d_in[15];
    float* out = (float*)d_out;

    float *p_allout, *p_a, *p_hn, *p_t1, *p_t3, *p_m2, *p_q, *p_k, *p_v;
    cudaGetSymbolAddress((void**)&p_allout, g_allout);
    cudaGetSymbolAddress((void**)&p_a,  g_a);
    cudaGetSymbolAddress((void**)&p_hn, g_hn);
    cudaGetSymbolAddress((void**)&p_t1, g_t1);
    cudaGetSymbolAddress((void**)&p_t3, g_t3);
    cudaGetSymbolAddress((void**)&p_m2, g_m2);
    cudaGetSymbolAddress((void**)&p_q,  g_q);
    cudaGetSymbolAddress((void**)&p_k,  g_k);
    cudaGetSymbolAddress((void**)&p_v,  g_v);

    cudaFuncSetAttribute(attn_kernel,
                         cudaFuncAttributeMaxDynamicSharedMemorySize, ATTN_SMEM);
    cudaFuncSetAttribute(mma_gemm_kernel<false>,
                         cudaFuncAttributeMaxDynamicSharedMemorySize, GEMM_SMEM);
    cudaFuncSetAttribute(mma_gemm_kernel<true>,
                         cudaFuncAttributeMaxDynamicSharedMemorySize, GEMM_SMEM);

    const long long MD  = (long long)M_ * D_;
    const long long LD  = (long long)L_ * D_;
    const long long MH  = (long long)M_ * HID_;
    const long long SD  = (long long)S_ * D_;

    for (int s = 0; s < NSTEP; s++) {
        const float* om = (s == 0) ? omem : (p_allout + (size_t)(s - 1) * M_ * D_);
        const long long omB = (s == 0) ? 0LL : SD;

        // a = om @ wm
        mma_gemm_kernel<false><<<dim3(8, 4, 2), 256, GEMM_SMEM>>>(
            om, omB, wm, wm, wm, p_a, p_a, p_a, MD, MD, MD, D_, D_, 8);
        // hn = rmsnorm(a, ffn_norm_w)
        rmsnorm_kernel<<<B_ * M_, 256>>>(p_a, ffn_nw, p_hn);
        // t1 = hn @ w1 ; t3 = hn @ w3 (fused)
        mma_gemm_kernel<false><<<dim3(44, 4, 2), 256, GEMM_SMEM>>>(
            p_hn, MD, w1, w3, w3, p_t1, p_t3, p_t3, MH, MH, MH, D_, HID_, 22);
        // t1 = silu(t1) * t3
        silu_gate_kernel<<<(B_ * M_ * HID_ + 255) / 256, 256>>>(p_t1, p_t3, B_ * M_ * HID_);
        // a += t1 @ w2
        mma_gemm_kernel<true><<<dim3(8, 4, 2), 256, GEMM_SMEM>>>(
            p_t1, MH, w2, w2, w2, p_a, p_a, p_a, MD, MD, MD, HID_, D_, 8);
        // m2 = rmsnorm(a, mem_norm_w)
        rmsnorm_kernel<<<B_ * M_, 256>>>(p_a, mem_nw, p_m2);
        // mk -> k[:, :512], mv -> v[:, :512] (fused)
        mma_gemm_kernel<false><<<dim3(16, 4, 2), 256, GEMM_SMEM>>>(
            p_m2, MD, wkm, wvm, wvm, p_k, p_v, p_v, LD, LD, LD, D_, D_, 8);
        // xq ; xk -> k[:, 512:] ; xv -> v[:, 512:] (fused)
        const float* xs = x + (size_t)s * M_ * D_;
        mma_gemm_kernel<false><<<dim3(24, 4, 2), 256, GEMM_SMEM>>>(
            xs, SD, wq, wk, wv, p_q, p_k + (size_t)M_ * D_, p_v + (size_t)M_ * D_,
            MD, LD, LD, D_, D_, 8);
        // RoPE
        {
            int nk = B_ * L_ * (D_ / 2);
            rope_kernel<<<(nk + 255) / 256, 256>>>(p_k, cosT, sinT, L_, 0, nk);
            int nq = B_ * M_ * (D_ / 2);
            rope_kernel<<<(nq + 255) / 256, 256>>>(p_q, cosT, sinT, M_, M_, nq);
        }
        // Attention
        attn_kernel<<<dim3(M_ / 64, H_, B_), 256, ATTN_SMEM>>>(p_q, p_k, p_v, p_allout, s * M_);
    }

    // out = allout @ wo
    mma_gemm_kernel<false><<<dim3(8, 64, 1), 256, GEMM_SMEM>>>(
        p_allout, 0LL, wo, wo, wo, out, out, out, 0LL, 0LL, 0LL, D_, D_, 8);
}